// round 4
// baseline (speedup 1.0000x reference)
#include <cuda_runtime.h>

// TabNet encoder, fully fused, packed f32x2 math, 512 threads/CTA.
// One CTA = 32 rows, all state in SMEM, 1 CTA/SM, 16 warps.
// B=131072, D=256, UN=128 (2UN=256), ND=NA=64, NSTEPS=3.

#define TB 32            // rows per CTA
#define NTH 512          // threads per CTA

typedef unsigned long long u64;

__device__ __forceinline__ u64 dup2(float v) {
    u64 r; asm("mov.b64 %0,{%1,%1};" : "=l"(r) : "f"(v)); return r;
}
__device__ __forceinline__ void fma2_(u64& d, u64 a, u64 b) {
    asm("fma.rn.f32x2 %0,%1,%2,%3;" : "=l"(d) : "l"(a), "l"(b), "l"(d));
}
__device__ __forceinline__ float2 up2(u64 v) {
    float lo, hi; asm("mov.b64 {%0,%1},%2;" : "=f"(lo), "=f"(hi) : "l"(v));
    return make_float2(lo, hi);
}

__device__ __forceinline__ float sig_(float x) {
    return __fdividef(1.0f, 1.0f + __expf(-x));
}

// H[TB][256] = BN(act[TB][AS..K] @ W[K][256]); thread tile 4 rows x 4 cols.
// cg = t&63 -> cols 4cg.., rg = t>>6 (0..7) -> rows 4rg..
template<int K, int AS>
__device__ __forceinline__ void gemm_bn256(
    const float* __restrict__ W,
    const float* __restrict__ gg, const float* __restrict__ bb,
    const float* __restrict__ mm, const float* __restrict__ vv,
    const float* act, float* H)
{
    const int t  = threadIdx.x;
    const int cg = t & 63;
    const int c0 = cg << 2;
    const int r0 = (t >> 6) << 2;
    const float* actb = act + r0 * AS;
    // W row = 256 floats = 64 ulonglong2; this thread reads element cg of each row.
    const ulonglong2* W2 = reinterpret_cast<const ulonglong2*>(W) + cg;

    u64 acc[4][2];
#pragma unroll
    for (int r = 0; r < 4; r++) { acc[r][0] = 0ull; acc[r][1] = 0ull; }

    ulonglong2 w[4];
#pragma unroll
    for (int i = 0; i < 4; i++) w[i] = W2[i * 64];

#pragma unroll 1
    for (int k = 0; k < K; k += 4) {
        const int kn = (k + 4 < K) ? (k + 4) : k;
        ulonglong2 wn[4];
#pragma unroll
        for (int i = 0; i < 4; i++) wn[i] = W2[(kn + i) * 64];

#pragma unroll
        for (int rr = 0; rr < 4; rr++) {
            float4 a4 = *reinterpret_cast<const float4*>(actb + rr * AS + k);
            u64 ax = dup2(a4.x), ay = dup2(a4.y);
            u64 az = dup2(a4.z), aw = dup2(a4.w);
            fma2_(acc[rr][0], ax, w[0].x); fma2_(acc[rr][1], ax, w[0].y);
            fma2_(acc[rr][0], ay, w[1].x); fma2_(acc[rr][1], ay, w[1].y);
            fma2_(acc[rr][0], az, w[2].x); fma2_(acc[rr][1], az, w[2].y);
            fma2_(acc[rr][0], aw, w[3].x); fma2_(acc[rr][1], aw, w[3].y);
        }
#pragma unroll
        for (int i = 0; i < 4; i++) w[i] = wn[i];
    }

    // folded-BN epilogue
    float sc[4], bs[4];
#pragma unroll
    for (int cc = 0; cc < 4; cc++) {
        int c = c0 + cc;
        sc[cc] = gg[c] * rsqrtf(vv[c] + 1e-3f);
        bs[cc] = bb[c] - mm[c] * sc[cc];
    }
#pragma unroll
    for (int rr = 0; rr < 4; rr++) {
        float2 lo = up2(acc[rr][0]), hi = up2(acc[rr][1]);
        float4 o;
        o.x = fmaf(lo.x, sc[0], bs[0]);
        o.y = fmaf(lo.y, sc[1], bs[1]);
        o.z = fmaf(hi.x, sc[2], bs[2]);
        o.w = fmaf(hi.y, sc[3], bs[3]);
        *reinterpret_cast<float4*>(H + (r0 + rr) * 256 + c0) = o;
    }
}

// GLU over H[TB][256]: out = H[:, :128] * sigmoid(H[:, 128:]).
__device__ __forceinline__ void glu_step(const float* H, float* outp, int os,
                                         const float* addp, int as_, bool combine)
{
    const int t = threadIdx.x;
    const int u = t & 127;
    const int q = t >> 7;                 // 0..3
#pragma unroll
    for (int r8 = 0; r8 < TB / 4; r8++) {
        int r = q * (TB / 4) + r8;
        float a = H[r * 256 + u];
        float b = H[r * 256 + 128 + u];
        float gl = a * sig_(b);
        if (combine) gl = 0.70710678118654752f * (addp[r * as_ + u] + gl);
        outp[r * os + u] = gl;
    }
}

template<int AS>
__device__ __forceinline__ void shared_block_(const float* act,
    const float* W0, const float* W1,
    const float* g, const float* b, const float* m, const float* v,
    float* X, float* H, float* G)
{
    __syncthreads();
    gemm_bn256<256, AS>(W0, g, b, m, v, act, H);
    __syncthreads();
    glu_step(H, G, 128, (const float*)0, 0, false);      // G = glu1
    __syncthreads();
    gemm_bn256<128, 128>(W1, g + 256, b + 256, m + 256, v + 256, G, H);
    __syncthreads();
    glu_step(H, X, 256, G, 128, true);                   // X[:, :128] = s*(glu1+glu2)
    __syncthreads();
}

__device__ __forceinline__ void dep_block_(const float* Wd, const float* g, const float* b,
    const float* m, const float* v, float* X, float* H)
{
#pragma unroll
    for (int i = 0; i < 2; i++) {
        __syncthreads();
        gemm_bn256<128, 256>(Wd + i * 128 * 256, g + i * 256, b + i * 256,
                             m + i * 256, v + i * 256, X, H);
        __syncthreads();
        glu_step(H, X, 256, X, 256, true);               // X = s*(X + glu)
    }
    __syncthreads();
}

__device__ __forceinline__ void post_dep_(const float* X, float* aB, float* agg, bool addagg)
{
#pragma unroll
    for (int i = 0; i < TB * 64 / NTH; i++) {
        int lin = threadIdx.x + NTH * i;
        int r = lin >> 6, c = lin & 63;
        aB[r * 64 + c] = X[r * 256 + 64 + c];
        if (addagg) agg[r * 64 + c] += fmaxf(X[r * 256 + c], 0.0f);
    }
    __syncthreads();
}

// z = prior * bn_logits (in H); sparsemax via Michelot projection; one warp = 2 rows.
__device__ __forceinline__ void attn_sparsemax_(const float* H, float* prior,
                                                const float* feat, float* X)
{
    const int warp = threadIdx.x >> 5;     // 0..15
    const int lane = threadIdx.x & 31;
#pragma unroll
    for (int rr = 0; rr < TB / 16; rr++) {
        const int r = warp * (TB / 16) + rr;
        float z[8];
#pragma unroll
        for (int i = 0; i < 8; i++) {
            int e = lane + 32 * i;
            z[i] = prior[r * 256 + e] * H[r * 256 + e];
        }
        unsigned am = 0xFFu;
        float tau = 0.0f;
        for (int it = 0; it < 64; it++) {
            float s = 0.0f, cnt = 0.0f;
#pragma unroll
            for (int i = 0; i < 8; i++)
                if (am & (1u << i)) { s += z[i]; cnt += 1.0f; }
#pragma unroll
            for (int o = 16; o >= 1; o >>= 1) {
                s   += __shfl_xor_sync(0xffffffffu, s, o);
                cnt += __shfl_xor_sync(0xffffffffu, cnt, o);
            }
            tau = __fdividef(s - 1.0f, cnt);
            unsigned na = 0u;
#pragma unroll
            for (int i = 0; i < 8; i++)
                if (z[i] > tau) na |= (1u << i);
            int changed = (na != am);
            am = na;
            if (!__any_sync(0xffffffffu, changed)) break;
        }
#pragma unroll
        for (int i = 0; i < 8; i++) {
            int e = lane + 32 * i;
            float mv = fmaxf(z[i] - tau, 0.0f);
            X[r * 256 + e] = mv * feat[r * 256 + e];
            prior[r * 256 + e] *= (1.3f - mv);
        }
    }
    __syncthreads();
}

__global__ void __launch_bounds__(NTH, 1)
tabnet_fused(const float* __restrict__ inputs,
             const float* __restrict__ in_g, const float* __restrict__ in_b,
             const float* __restrict__ in_m, const float* __restrict__ in_v,
             const float* __restrict__ sh_W0, const float* __restrict__ sh_W1,
             const float* __restrict__ sh_g, const float* __restrict__ sh_b,
             const float* __restrict__ sh_m, const float* __restrict__ sh_v,
             const float* __restrict__ dep_W, const float* __restrict__ dep_g,
             const float* __restrict__ dep_b, const float* __restrict__ dep_m,
             const float* __restrict__ dep_v,
             const float* __restrict__ at_W, const float* __restrict__ at_g,
             const float* __restrict__ at_b, const float* __restrict__ at_m,
             const float* __restrict__ at_v,
             const float* __restrict__ Wout,
             float* __restrict__ out, int B)
{
    extern __shared__ float sm_[];
    float* feat  = sm_;                 // [TB][256]
    float* prior = feat  + TB * 256;    // [TB][256]
    float* X     = prior + TB * 256;    // [TB][256]
    float* H     = X     + TB * 256;    // [TB][256]
    float* G     = H     + TB * 256;    // [TB][128]
    float* aB    = G     + TB * 128;    // [TB][64]
    float* agg   = aB    + TB * 64;     // [TB][64]

    const int t = threadIdx.x;
    const long long rowbase = (long long)blockIdx.x * TB;

    // input BN -> feat; prior = 1; agg = 0
    {
        const float4* in4 = reinterpret_cast<const float4*>(inputs);
        const float4* g4  = reinterpret_cast<const float4*>(in_g);
        const float4* b4  = reinterpret_cast<const float4*>(in_b);
        const float4* m4  = reinterpret_cast<const float4*>(in_m);
        const float4* v4  = reinterpret_cast<const float4*>(in_v);
#pragma unroll
        for (int i = 0; i < TB * 64 / NTH; i++) {
            int lin = t + NTH * i;           // float4 index
            int r = lin >> 6, d4 = lin & 63;
            long long gr = rowbase + r; if (gr >= B) gr = B - 1;
            float4 xv = in4[gr * 64 + d4];
            float4 gv = g4[d4], bv = b4[d4], mv = m4[d4], vv = v4[d4];
            float4 o; float s;
            s = gv.x * rsqrtf(vv.x + 1e-3f); o.x = fmaf(xv.x - mv.x, s, bv.x);
            s = gv.y * rsqrtf(vv.y + 1e-3f); o.y = fmaf(xv.y - mv.y, s, bv.y);
            s = gv.z * rsqrtf(vv.z + 1e-3f); o.z = fmaf(xv.z - mv.z, s, bv.z);
            s = gv.w * rsqrtf(vv.w + 1e-3f); o.w = fmaf(xv.w - mv.w, s, bv.w);
            reinterpret_cast<float4*>(feat)[lin] = o;
            reinterpret_cast<float4*>(prior)[lin] = make_float4(1.f, 1.f, 1.f, 1.f);
        }
        reinterpret_cast<float4*>(agg)[t] = make_float4(0.f, 0.f, 0.f, 0.f);
    }
    __syncthreads();

    // initial shared + dep block (no agg accumulation)
    shared_block_<256>(feat, sh_W0, sh_W1, sh_g, sh_b, sh_m, sh_v, X, H, G);
    dep_block_(dep_W, dep_g, dep_b, dep_m, dep_v, X, H);
    post_dep_(X, aB, agg, false);

    // 3 decision steps
    for (int s = 0; s < 3; s++) {
        __syncthreads();
        gemm_bn256<64, 64>(at_W + s * 64 * 256, at_g + s * 256, at_b + s * 256,
                           at_m + s * 256, at_v + s * 256, aB, H);
        __syncthreads();
        attn_sparsemax_(H, prior, feat, X);   // X = mask * feat
        shared_block_<256>(X, sh_W0, sh_W1, sh_g, sh_b, sh_m, sh_v, X, H, G);
        dep_block_(dep_W + (s + 1) * 2 * 128 * 256,
                   dep_g + (s + 1) * 512, dep_b + (s + 1) * 512,
                   dep_m + (s + 1) * 512, dep_v + (s + 1) * 512, X, H);
        post_dep_(X, aB, agg, true);
    }

    // out = agg @ Wout  (64x64); rg = t>>6 (0..7) -> 4 rows each
    {
        const int c   = t & 63;
        const int rgx = t >> 6;
        float acc[4];
#pragma unroll
        for (int rr = 0; rr < 4; rr++) acc[rr] = 0.0f;
        for (int k = 0; k < 64; k += 4) {
#pragma unroll
            for (int kk = 0; kk < 4; kk++) {
                float wv_ = Wout[(k + kk) * 64 + c];
#pragma unroll
                for (int rr = 0; rr < 4; rr++)
                    acc[rr] = fmaf(agg[(rgx * 4 + rr) * 64 + (k + kk)], wv_, acc[rr]);
            }
        }
#pragma unroll
        for (int rr = 0; rr < 4; rr++) {
            long long gr = rowbase + rgx * 4 + rr;
            if (gr < B) out[gr * 64 + c] = acc[rr];
        }
    }
}

extern "C" void kernel_launch(void* const* d_in, const int* in_sizes, int n_in,
                              void* d_out, int out_size)
{
    const float* inputs = (const float*)d_in[0];
    const float* in_g   = (const float*)d_in[1];
    const float* in_b   = (const float*)d_in[2];
    const float* in_m   = (const float*)d_in[3];
    const float* in_v   = (const float*)d_in[4];
    const float* sh_W0  = (const float*)d_in[5];
    const float* sh_W1  = (const float*)d_in[6];
    const float* sh_g   = (const float*)d_in[7];
    const float* sh_b   = (const float*)d_in[8];
    const float* sh_m   = (const float*)d_in[9];
    const float* sh_v   = (const float*)d_in[10];
    const float* dep_W  = (const float*)d_in[11];
    const float* dep_g  = (const float*)d_in[12];
    const float* dep_b  = (const float*)d_in[13];
    const float* dep_m  = (const float*)d_in[14];
    const float* dep_v  = (const float*)d_in[15];
    const float* at_W   = (const float*)d_in[16];
    const float* at_g   = (const float*)d_in[17];
    const float* at_b   = (const float*)d_in[18];
    const float* at_m   = (const float*)d_in[19];
    const float* at_v   = (const float*)d_in[20];
    const float* Wout   = (const float*)d_in[21];

    int B = in_sizes[0] / 256;
    int grid = (B + TB - 1) / TB;
    size_t smem = (size_t)(TB * 256 * 4 + TB * 128 + TB * 64 * 2) * sizeof(float); // 160 KB

    cudaFuncSetAttribute(tabnet_fused, cudaFuncAttributeMaxDynamicSharedMemorySize, (int)smem);
    tabnet_fused<<<grid, NTH, smem>>>(inputs, in_g, in_b, in_m, in_v,
                                      sh_W0, sh_W1, sh_g, sh_b, sh_m, sh_v,
                                      dep_W, dep_g, dep_b, dep_m, dep_v,
                                      at_W, at_g, at_b, at_m, at_v,
                                      Wout, (float*)d_out, B);
}

// round 5
// speedup vs baseline: 1.1913x; 1.1913x over previous
#include <cuda_runtime.h>

// TabNet encoder, fully fused, packed f32x2 math.
// One CTA = 48 rows, 384 threads (12 warps, 3/SMSP), 1 CTA/SM.
// prior lives in GMEM scratch (__device__ array); rest of state in SMEM (192KB).
// B=131072, D=256, UN=128 (2UN=256), ND=NA=64, NSTEPS=3.

#define TB 48            // rows per CTA
#define NTH 384          // threads per CTA
#define BMAX 131072

__device__ float g_prior[(size_t)BMAX * 256];

typedef unsigned long long u64;

__device__ __forceinline__ u64 dup2(float v) {
    u64 r; asm("mov.b64 %0,{%1,%1};" : "=l"(r) : "f"(v)); return r;
}
__device__ __forceinline__ void fma2_(u64& d, u64 a, u64 b) {
    asm("fma.rn.f32x2 %0,%1,%2,%3;" : "=l"(d) : "l"(a), "l"(b), "l"(d));
}
__device__ __forceinline__ float2 up2(u64 v) {
    float lo, hi; asm("mov.b64 {%0,%1},%2;" : "=f"(lo), "=f"(hi) : "l"(v));
    return make_float2(lo, hi);
}

__device__ __forceinline__ float sig_(float x) {
    return __fdividef(1.0f, 1.0f + __expf(-x));
}

// H[TB][256] = BN(act[TB][AS..K] @ W[K][256]); thread tile 8 rows x 4 cols.
// cg = t&63 -> cols 4cg.., rg = t>>6 (0..5) -> rows 8rg..
template<int K, int AS>
__device__ __forceinline__ void gemm_bn256(
    const float* __restrict__ W,
    const float* __restrict__ gg, const float* __restrict__ bb,
    const float* __restrict__ mm, const float* __restrict__ vv,
    const float* act, float* H)
{
    const int t  = threadIdx.x;
    const int cg = t & 63;
    const int c0 = cg << 2;
    const int r0 = (t >> 6) << 3;
    const float* actb = act + r0 * AS;
    // W row = 256 floats = 64 ulonglong2; this thread reads element cg of each row.
    const ulonglong2* W2 = reinterpret_cast<const ulonglong2*>(W) + cg;

    u64 acc[8][2];
#pragma unroll
    for (int r = 0; r < 8; r++) { acc[r][0] = 0ull; acc[r][1] = 0ull; }

    ulonglong2 w[4];
#pragma unroll
    for (int i = 0; i < 4; i++) w[i] = W2[i * 64];

#pragma unroll 1
    for (int k = 0; k < K; k += 4) {
        const int kn = (k + 4 < K) ? (k + 4) : k;
        ulonglong2 wn[4];
#pragma unroll
        for (int i = 0; i < 4; i++) wn[i] = W2[(kn + i) * 64];

#pragma unroll
        for (int rr = 0; rr < 8; rr++) {
            float4 a4 = *reinterpret_cast<const float4*>(actb + rr * AS + k);
            u64 ax = dup2(a4.x), ay = dup2(a4.y);
            u64 az = dup2(a4.z), aw = dup2(a4.w);
            fma2_(acc[rr][0], ax, w[0].x); fma2_(acc[rr][1], ax, w[0].y);
            fma2_(acc[rr][0], ay, w[1].x); fma2_(acc[rr][1], ay, w[1].y);
            fma2_(acc[rr][0], az, w[2].x); fma2_(acc[rr][1], az, w[2].y);
            fma2_(acc[rr][0], aw, w[3].x); fma2_(acc[rr][1], aw, w[3].y);
        }
#pragma unroll
        for (int i = 0; i < 4; i++) w[i] = wn[i];
    }

    // folded-BN epilogue
    float sc[4], bs[4];
#pragma unroll
    for (int cc = 0; cc < 4; cc++) {
        int c = c0 + cc;
        sc[cc] = gg[c] * rsqrtf(vv[c] + 1e-3f);
        bs[cc] = bb[c] - mm[c] * sc[cc];
    }
#pragma unroll
    for (int rr = 0; rr < 8; rr++) {
        float2 lo = up2(acc[rr][0]), hi = up2(acc[rr][1]);
        float4 o;
        o.x = fmaf(lo.x, sc[0], bs[0]);
        o.y = fmaf(lo.y, sc[1], bs[1]);
        o.z = fmaf(hi.x, sc[2], bs[2]);
        o.w = fmaf(hi.y, sc[3], bs[3]);
        *reinterpret_cast<float4*>(H + (r0 + rr) * 256 + c0) = o;
    }
}

// GLU over H[TB][256]: out = H[:, :128] * sigmoid(H[:, 128:]).
__device__ __forceinline__ void glu_step(const float* H, float* outp, int os,
                                         const float* addp, int as_, bool combine)
{
    const int t = threadIdx.x;
    const int u = t & 127;
    const int q = t >> 7;                 // 0..2
#pragma unroll
    for (int r8 = 0; r8 < TB / 3; r8++) {
        int r = q * (TB / 3) + r8;
        float a = H[r * 256 + u];
        float b = H[r * 256 + 128 + u];
        float gl = a * sig_(b);
        if (combine) gl = 0.70710678118654752f * (addp[r * as_ + u] + gl);
        outp[r * os + u] = gl;
    }
}

template<int AS>
__device__ __forceinline__ void shared_block_(const float* act,
    const float* W0, const float* W1,
    const float* g, const float* b, const float* m, const float* v,
    float* X, float* H, float* G)
{
    __syncthreads();
    gemm_bn256<256, AS>(W0, g, b, m, v, act, H);
    __syncthreads();
    glu_step(H, G, 128, (const float*)0, 0, false);      // G = glu1
    __syncthreads();
    gemm_bn256<128, 128>(W1, g + 256, b + 256, m + 256, v + 256, G, H);
    __syncthreads();
    glu_step(H, X, 256, G, 128, true);                   // X[:, :128] = s*(glu1+glu2)
    __syncthreads();
}

__device__ __forceinline__ void dep_block_(const float* Wd, const float* g, const float* b,
    const float* m, const float* v, float* X, float* H)
{
#pragma unroll
    for (int i = 0; i < 2; i++) {
        __syncthreads();
        gemm_bn256<128, 256>(Wd + i * 128 * 256, g + i * 256, b + i * 256,
                             m + i * 256, v + i * 256, X, H);
        __syncthreads();
        glu_step(H, X, 256, X, 256, true);               // X = s*(X + glu)
    }
    __syncthreads();
}

__device__ __forceinline__ void post_dep_(const float* X, float* aB, float* agg, bool addagg)
{
#pragma unroll
    for (int i = 0; i < TB * 64 / NTH; i++) {
        int lin = threadIdx.x + NTH * i;
        int r = lin >> 6, c = lin & 63;
        aB[r * 64 + c] = X[r * 256 + 64 + c];
        if (addagg) agg[r * 64 + c] += fmaxf(X[r * 256 + c], 0.0f);
    }
    __syncthreads();
}

// z = prior * bn_logits (in H); sparsemax via Michelot projection; one warp = 4 rows.
// prior read from / written to GMEM scratch; step 0 uses implicit prior=1.
__device__ __forceinline__ void attn_sparsemax_(const float* H, const float* feat,
                                                float* X, long long rowbase, int B,
                                                int step)
{
    const int warp = threadIdx.x >> 5;     // 0..11
    const int lane = threadIdx.x & 31;
#pragma unroll
    for (int rr = 0; rr < TB / 12; rr++) {
        const int r = warp * (TB / 12) + rr;
        long long gr = rowbase + r; if (gr >= B) gr = B - 1;
        float* pp = g_prior + gr * 256;

        float pv[8], z[8];
#pragma unroll
        for (int i = 0; i < 8; i++) {
            int e = lane + 32 * i;
            pv[i] = (step == 0) ? 1.0f : pp[e];
            z[i] = pv[i] * H[r * 256 + e];
        }
        unsigned am = 0xFFu;
        float tau = 0.0f;
        for (int it = 0; it < 64; it++) {
            float s = 0.0f, cnt = 0.0f;
#pragma unroll
            for (int i = 0; i < 8; i++)
                if (am & (1u << i)) { s += z[i]; cnt += 1.0f; }
#pragma unroll
            for (int o = 16; o >= 1; o >>= 1) {
                s   += __shfl_xor_sync(0xffffffffu, s, o);
                cnt += __shfl_xor_sync(0xffffffffu, cnt, o);
            }
            tau = __fdividef(s - 1.0f, cnt);
            unsigned na = 0u;
#pragma unroll
            for (int i = 0; i < 8; i++)
                if (z[i] > tau) na |= (1u << i);
            int changed = (na != am);
            am = na;
            if (!__any_sync(0xffffffffu, changed)) break;
        }
#pragma unroll
        for (int i = 0; i < 8; i++) {
            int e = lane + 32 * i;
            float mv = fmaxf(z[i] - tau, 0.0f);
            X[r * 256 + e] = mv * feat[r * 256 + e];
            if (step < 2) pp[e] = pv[i] * (1.3f - mv);   // last step's prior unused
        }
    }
    __syncthreads();
}

__global__ void __launch_bounds__(NTH, 1)
tabnet_fused(const float* __restrict__ inputs,
             const float* __restrict__ in_g, const float* __restrict__ in_b,
             const float* __restrict__ in_m, const float* __restrict__ in_v,
             const float* __restrict__ sh_W0, const float* __restrict__ sh_W1,
             const float* __restrict__ sh_g, const float* __restrict__ sh_b,
             const float* __restrict__ sh_m, const float* __restrict__ sh_v,
             const float* __restrict__ dep_W, const float* __restrict__ dep_g,
             const float* __restrict__ dep_b, const float* __restrict__ dep_m,
             const float* __restrict__ dep_v,
             const float* __restrict__ at_W, const float* __restrict__ at_g,
             const float* __restrict__ at_b, const float* __restrict__ at_m,
             const float* __restrict__ at_v,
             const float* __restrict__ Wout,
             float* __restrict__ out, int B)
{
    extern __shared__ float sm_[];
    float* feat  = sm_;                 // [TB][256]
    float* X     = feat  + TB * 256;    // [TB][256]
    float* H     = X     + TB * 256;    // [TB][256]
    float* G     = H     + TB * 256;    // [TB][128]
    float* aB    = G     + TB * 128;    // [TB][64]
    float* agg   = aB    + TB * 64;     // [TB][64]

    const int t = threadIdx.x;
    const long long rowbase = (long long)blockIdx.x * TB;

    // input BN -> feat; agg = 0
    {
        const float4* in4 = reinterpret_cast<const float4*>(inputs);
        const float4* g4  = reinterpret_cast<const float4*>(in_g);
        const float4* b4  = reinterpret_cast<const float4*>(in_b);
        const float4* m4  = reinterpret_cast<const float4*>(in_m);
        const float4* v4  = reinterpret_cast<const float4*>(in_v);
#pragma unroll
        for (int i = 0; i < TB * 64 / NTH; i++) {
            int lin = t + NTH * i;           // float4 index
            int r = lin >> 6, d4 = lin & 63;
            long long gr = rowbase + r; if (gr >= B) gr = B - 1;
            float4 xv = in4[gr * 64 + d4];
            float4 gv = g4[d4], bv = b4[d4], mv = m4[d4], vv = v4[d4];
            float4 o; float s;
            s = gv.x * rsqrtf(vv.x + 1e-3f); o.x = fmaf(xv.x - mv.x, s, bv.x);
            s = gv.y * rsqrtf(vv.y + 1e-3f); o.y = fmaf(xv.y - mv.y, s, bv.y);
            s = gv.z * rsqrtf(vv.z + 1e-3f); o.z = fmaf(xv.z - mv.z, s, bv.z);
            s = gv.w * rsqrtf(vv.w + 1e-3f); o.w = fmaf(xv.w - mv.w, s, bv.w);
            reinterpret_cast<float4*>(feat)[lin] = o;
        }
#pragma unroll
        for (int i = 0; i < (TB * 16 + NTH - 1) / NTH; i++) {
            int lin = t + NTH * i;
            if (lin < TB * 16)
                reinterpret_cast<float4*>(agg)[lin] = make_float4(0.f, 0.f, 0.f, 0.f);
        }
    }
    __syncthreads();

    // initial shared + dep block (no agg accumulation)
    shared_block_<256>(feat, sh_W0, sh_W1, sh_g, sh_b, sh_m, sh_v, X, H, G);
    dep_block_(dep_W, dep_g, dep_b, dep_m, dep_v, X, H);
    post_dep_(X, aB, agg, false);

    // 3 decision steps
    for (int s = 0; s < 3; s++) {
        __syncthreads();
        gemm_bn256<64, 64>(at_W + s * 64 * 256, at_g + s * 256, at_b + s * 256,
                           at_m + s * 256, at_v + s * 256, aB, H);
        __syncthreads();
        attn_sparsemax_(H, feat, X, rowbase, B, s);   // X = mask * feat
        shared_block_<256>(X, sh_W0, sh_W1, sh_g, sh_b, sh_m, sh_v, X, H, G);
        dep_block_(dep_W + (s + 1) * 2 * 128 * 256,
                   dep_g + (s + 1) * 512, dep_b + (s + 1) * 512,
                   dep_m + (s + 1) * 512, dep_v + (s + 1) * 512, X, H);
        post_dep_(X, aB, agg, true);
    }

    // out = agg @ Wout  (64x64); rgx = t>>6 (0..5) -> 8 rows each
    {
        const int c   = t & 63;
        const int rgx = t >> 6;
        float acc[8];
#pragma unroll
        for (int rr = 0; rr < 8; rr++) acc[rr] = 0.0f;
        for (int k = 0; k < 64; k += 4) {
#pragma unroll
            for (int kk = 0; kk < 4; kk++) {
                float wv_ = Wout[(k + kk) * 64 + c];
#pragma unroll
                for (int rr = 0; rr < 8; rr++)
                    acc[rr] = fmaf(agg[(rgx * 8 + rr) * 64 + (k + kk)], wv_, acc[rr]);
            }
        }
#pragma unroll
        for (int rr = 0; rr < 8; rr++) {
            long long gr = rowbase + rgx * 8 + rr;
            if (gr < B) out[gr * 64 + c] = acc[rr];
        }
    }
}

extern "C" void kernel_launch(void* const* d_in, const int* in_sizes, int n_in,
                              void* d_out, int out_size)
{
    const float* inputs = (const float*)d_in[0];
    const float* in_g   = (const float*)d_in[1];
    const float* in_b   = (const float*)d_in[2];
    const float* in_m   = (const float*)d_in[3];
    const float* in_v   = (const float*)d_in[4];
    const float* sh_W0  = (const float*)d_in[5];
    const float* sh_W1  = (const float*)d_in[6];
    const float* sh_g   = (const float*)d_in[7];
    const float* sh_b   = (const float*)d_in[8];
    const float* sh_m   = (const float*)d_in[9];
    const float* sh_v   = (const float*)d_in[10];
    const float* dep_W  = (const float*)d_in[11];
    const float* dep_g  = (const float*)d_in[12];
    const float* dep_b  = (const float*)d_in[13];
    const float* dep_m  = (const float*)d_in[14];
    const float* dep_v  = (const float*)d_in[15];
    const float* at_W   = (const float*)d_in[16];
    const float* at_g   = (const float*)d_in[17];
    const float* at_b   = (const float*)d_in[18];
    const float* at_m   = (const float*)d_in[19];
    const float* at_v   = (const float*)d_in[20];
    const float* Wout   = (const float*)d_in[21];

    int B = in_sizes[0] / 256;
    int grid = (B + TB - 1) / TB;
    size_t smem = (size_t)(TB * 256 * 3 + TB * 128 + TB * 64 * 2) * sizeof(float); // 192 KB

    cudaFuncSetAttribute(tabnet_fused, cudaFuncAttributeMaxDynamicSharedMemorySize, (int)smem);
    tabnet_fused<<<grid, NTH, smem>>>(inputs, in_g, in_b, in_m, in_v,
                                      sh_W0, sh_W1, sh_g, sh_b, sh_m, sh_v,
                                      dep_W, dep_g, dep_b, dep_m, dep_v,
                                      at_W, at_g, at_b, at_m, at_v,
                                      Wout, (float*)d_out, B);
}